// round 5
// baseline (speedup 1.0000x reference)
#include <cuda_runtime.h>
#include <cstdint>

// mean_var_norm — (B=64, F=256, T=4000) fp32.
// Persistent CTAs + cp.async.bulk (1D TMA) smem ring pipeline:
//   - grid=296 (2 CTAs/SM), 256 threads
//   - 6-stage ring of 16KB row buffers in dynamic smem, mbarrier per slot
//   - tid0 issues bulk loads 6 rows ahead; bulk engine keeps DRAM fed
//     through the reduction bubble (no register cost for in-flight data)
//   - compute: smem -> regs once (accumulate + hold), reduce, normalize,
//     streaming stores straight from regs.

#define BN 64
#define FN 256
#define TN 4000
#define FQ (TN / 4)            // 1000 float4 per row
#define THREADS 256
#define NW (THREADS / 32)
#define NROWS (BN * FN)        // 16384
#define GRID 296               // 2 per SM, persistent
#define S 6                    // pipeline stages
#define SLOT_BYTES 16384       // 16000 used, padded
#define ROW_BYTES 16000

__device__ __forceinline__ uint32_t smem_u32(const void* p) {
    uint32_t a;
    asm("{ .reg .u64 t; cvta.to.shared.u64 t, %1; cvt.u32.u64 %0, t; }"
        : "=r"(a) : "l"(p));
    return a;
}

__device__ __forceinline__ void mbar_init(uint32_t mbar, uint32_t cnt) {
    asm volatile("mbarrier.init.shared.b64 [%0], %1;" :: "r"(mbar), "r"(cnt) : "memory");
}

__device__ __forceinline__ void mbar_expect_tx(uint32_t mbar, uint32_t bytes) {
    asm volatile("mbarrier.arrive.expect_tx.shared.b64 _, [%0], %1;"
                 :: "r"(mbar), "r"(bytes) : "memory");
}

__device__ __forceinline__ void mbar_wait(uint32_t mbar, uint32_t parity) {
    asm volatile(
        "{\n\t"
        ".reg .pred P;\n\t"
        "WL_%=:\n\t"
        "mbarrier.try_wait.parity.acquire.cta.shared::cta.b64 P, [%0], %1, 0x989680;\n\t"
        "@P bra.uni WD_%=;\n\t"
        "bra.uni WL_%=;\n\t"
        "WD_%=:\n\t"
        "}"
        :: "r"(mbar), "r"(parity) : "memory");
}

__device__ __forceinline__ void bulk_load(uint32_t dst_smem, const void* src,
                                          uint32_t bytes, uint32_t mbar) {
    asm volatile(
        "cp.async.bulk.shared::cta.global.mbarrier::complete_tx::bytes "
        "[%0], [%1], %2, [%3];"
        :: "r"(dst_smem), "l"(src), "r"(bytes), "r"(mbar) : "memory");
}

extern __shared__ char ring[];   // S * SLOT_BYTES

__global__ void __launch_bounds__(THREADS, 2)
mvn_kernel(const float* __restrict__ x,
           const float* __restrict__ lengths,
           float* __restrict__ out) {
    const int tid  = threadIdx.x;
    const int bid  = blockIdx.x;
    const int wid  = tid >> 5;
    const int lane = tid & 31;

    __shared__ unsigned long long mbar_store[S];
    __shared__ float red[2][NW];
    __shared__ float bc[2];

    const uint32_t mb0 = smem_u32(&mbar_store[0]);
    const uint32_t slot0 = smem_u32(ring);

    if (tid == 0) {
        #pragma unroll
        for (int s = 0; s < S; s++) mbar_init(mb0 + 8u * s, 1);
    }
    __syncthreads();

    // rows: bid, bid+GRID, ...
    const int count = (NROWS - bid + GRID - 1) / GRID;

    // ---- prologue: fill the pipeline ----
    if (tid == 0) {
        const int pro = (count < S) ? count : S;
        for (int j = 0; j < pro; j++) {
            const long long row = bid + (long long)j * GRID;
            mbar_expect_tx(mb0 + 8u * j, ROW_BYTES);
            bulk_load(slot0 + (uint32_t)j * SLOT_BYTES,
                      x + row * TN, ROW_BYTES, mb0 + 8u * j);
        }
    }

    int slot = 0, phase = 0;
    for (int it = 0; it < count; it++) {
        const int row = bid + it * GRID;
        const int b   = row >> 8;                      // FN = 256
        const float nf = rintf(__ldg(&lengths[b]) * (float)TN);  // jnp.round
        const int   ni = (int)nf;

        mbar_wait(mb0 + 8u * slot, (uint32_t)phase);

        // ---- read row smem -> regs, masked accumulate ----
        const float4* __restrict__ sp =
            reinterpret_cast<const float4*>(ring + slot * SLOT_BYTES);
        float4 v[4];
        float s = 0.0f, ss = 0.0f;
        #pragma unroll
        for (int k = 0; k < 4; k++) {
            const int i4 = tid + k * THREADS;
            if (i4 < FQ) {
                v[k] = sp[i4];
                const int t0 = i4 * 4;
                if (t0 + 3 < ni) {
                    s  += v[k].x + v[k].y + v[k].z + v[k].w;
                    ss += v[k].x * v[k].x + v[k].y * v[k].y
                        + v[k].z * v[k].z + v[k].w * v[k].w;
                } else if (t0 < ni) {
                    if (t0 + 0 < ni) { s += v[k].x; ss += v[k].x * v[k].x; }
                    if (t0 + 1 < ni) { s += v[k].y; ss += v[k].y * v[k].y; }
                    if (t0 + 2 < ni) { s += v[k].z; ss += v[k].z * v[k].z; }
                    if (t0 + 3 < ni) { s += v[k].w; ss += v[k].w * v[k].w; }
                }
            }
        }

        // ---- block reduction (2 values) ----
        #pragma unroll
        for (int off = 16; off > 0; off >>= 1) {
            s  += __shfl_xor_sync(0xFFFFFFFFu, s,  off);
            ss += __shfl_xor_sync(0xFFFFFFFFu, ss, off);
        }
        if (lane == 0) { red[0][wid] = s; red[1][wid] = ss; }
        __syncthreads();   // also: all slot reads complete past this point

        if (tid == 0) {
            float sum = 0.0f, sumsq = 0.0f;
            #pragma unroll
            for (int w = 0; w < NW; w++) { sum += red[0][w]; sumsq += red[1][w]; }
            const float mean = sum / nf;
            float var = (sumsq - nf * mean * mean) / (nf - 1.0f);
            var = fmaxf(var, 0.0f);
            bc[0] = mean;
            bc[1] = 1.0f / fmaxf(sqrtf(var), 1e-10f);
        }
        __syncthreads();

        // ---- re-arm this slot with the row S ahead (slot reads are done) ----
        if (tid == 0) {
            const int nx = it + S;
            if (nx < count) {
                const long long rown = bid + (long long)nx * GRID;
                mbar_expect_tx(mb0 + 8u * slot, ROW_BYTES);
                bulk_load(slot0 + (uint32_t)slot * SLOT_BYTES,
                          x + rown * TN, ROW_BYTES, mb0 + 8u * slot);
            }
        }

        const float mean = bc[0];
        const float istd = bc[1];

        // ---- normalize from regs, streaming stores ----
        float4* __restrict__ op =
            reinterpret_cast<float4*>(out + (long long)row * TN);
        #pragma unroll
        for (int k = 0; k < 4; k++) {
            const int i4 = tid + k * THREADS;
            if (i4 < FQ) {
                float4 o;
                o.x = (v[k].x - mean) * istd;
                o.y = (v[k].y - mean) * istd;
                o.z = (v[k].z - mean) * istd;
                o.w = (v[k].w - mean) * istd;
                __stcs(&op[i4], o);
            }
        }

        if (++slot == S) { slot = 0; phase ^= 1; }
    }
}

extern "C" void kernel_launch(void* const* d_in, const int* in_sizes, int n_in,
                              void* d_out, int out_size) {
    const float* x       = (const float*)d_in[0];
    const float* lengths = (const float*)d_in[1];
    float* out           = (float*)d_out;

    static_assert(S * SLOT_BYTES == 98304, "smem size");
    cudaFuncSetAttribute(mvn_kernel,
                         cudaFuncAttributeMaxDynamicSharedMemorySize,
                         S * SLOT_BYTES);
    mvn_kernel<<<GRID, THREADS, S * SLOT_BYTES>>>(x, lengths, out);
}